// round 4
// baseline (speedup 1.0000x reference)
#include <cuda_runtime.h>
#include <cstdint>

#define NTOK 65536
#define DM   256
#define NE   8
#define MT   64
#define TPE  (NTOK / MT)          // 1024
#define GT   256
#define CHUNK_WORDS 8192          // 32 k x 256 n tf32 words
#define CHUNK_BYTES 32768
#define NBUF 4
#define NCHUNK_TOT 16             // 8 chunks W1 + 8 chunks W2

// ---------------- device scratch (no allocation allowed) -------------------
__device__ int   g_cnt[NE];
__device__ int   g_off[NE];
__device__ int   g_assign[NTOK];
__device__ int   g_ticket[NTOK];
__device__ float g_gate[NTOK];
__device__ int   g_perm[NTOK];
// fragment-ordered tf32 weight images: [e][chunk 0..15][8192 words]  (4 MB)
__device__ float g_wimg[NE * NCHUNK_TOT * CHUNK_WORDS];

// ---------------- SMEM layout for GEMM kernel (bytes) ----------------------
#define SM_TOK   0                // 64 ints
#define SM_GATE  256              // 64 floats
#define SM_BIAS  512              // 512 floats (b1 then b2)
#define SM_A     4096             // 16 k16 x 64 m x 16 floats = 65536 B
#define SM_B     69632            // 4 x 32768 B ring
#define SMEM_TOTAL 200704

// ---------------- helpers ---------------------------------------------------
__device__ __forceinline__ uint32_t f2tf32(float f) {
    uint32_t r;
    asm("cvt.rna.tf32.f32 %0, %1;" : "=r"(r) : "f"(f));
    return r;
}
__device__ __forceinline__ uint32_t smem_u32(const void* p) {
    uint32_t a;
    asm("{ .reg .u64 t; cvta.to.shared.u64 t, %1; cvt.u32.u64 %0, t; }"
        : "=r"(a) : "l"(p));
    return a;
}
__device__ __forceinline__ void mma_tf32(float c[4],
                                         uint32_t a0, uint32_t a1, uint32_t a2, uint32_t a3,
                                         uint32_t b0, uint32_t b1) {
    asm volatile(
        "mma.sync.aligned.m16n8k8.row.col.f32.tf32.tf32.f32 "
        "{%0,%1,%2,%3}, {%4,%5,%6,%7}, {%8,%9}, {%0,%1,%2,%3};\n"
        : "+f"(c[0]), "+f"(c[1]), "+f"(c[2]), "+f"(c[3])
        : "r"(a0), "r"(a1), "r"(a2), "r"(a3), "r"(b0), "r"(b1));
}
__device__ __forceinline__ void cp_async16(uint32_t dst, const void* src) {
    asm volatile("cp.async.cg.shared.global [%0], [%1], 16;"
                 :: "r"(dst), "l"(__cvta_generic_to_global(src)) : "memory");
}
__device__ __forceinline__ void cp_commit() {
    asm volatile("cp.async.commit_group;" ::: "memory");
}
__device__ __forceinline__ void cp_wait3() {
    asm volatile("cp.async.wait_group 3;" ::: "memory");
}

// ---------------- kernel 0: zero counters ----------------------------------
__global__ void zero_kernel() {
    if (threadIdx.x < NE) g_cnt[threadIdx.x] = 0;
}

// ---------------- kernel 1: weight -> fragment image ------------------------
// Chunk layout (8192 words): word[(kl>>4)*4096 + n*16 + (kl&3)*4 + ((kl>>2)&3)]
// holds tf32(W[kb*32 + kl][n]). This makes each thread's B fragment for two
// k8 steps one contiguous LDS.128.
__global__ void __launch_bounds__(256) wimg_kernel(
    const float* __restrict__ W1, const float* __restrict__ W2)
{
    __shared__ float img[CHUNK_WORDS];
    int b = blockIdx.x;                 // 128 blocks
    int e = b >> 4, stage = (b >> 3) & 1, kb = b & 7;
    const float* src = (stage ? W2 : W1) + (size_t)e * DM * DM + kb * 32 * DM;

    for (int i = threadIdx.x; i < CHUNK_WORDS; i += 256) {
        int n = i & 255, kl = i >> 8;   // coalesced over n
        float v = src[kl * DM + n];
        int j = (kl & 3) * 4 + ((kl >> 2) & 3);
        img[((kl >> 4) << 12) + n * 16 + j] = __uint_as_float(f2tf32(v));
    }
    __syncthreads();
    float4* d4 = (float4*)(g_wimg + ((size_t)e * NCHUNK_TOT + stage * 8 + kb) * CHUNK_WORDS);
    const float4* s4 = (const float4*)img;
    for (int i = threadIdx.x; i < CHUNK_WORDS / 4; i += 256) d4[i] = s4[i];
}

// ---------------- kernel 2: routing -----------------------------------------
// 256 threads / 128 tokens per block; 2 threads split K per token.
__global__ void __launch_bounds__(256) routing_kernel(
    const float* __restrict__ x, const float* __restrict__ wg)
{
    extern __shared__ float sm[];
    float* xS  = sm;                    // 128 rows x 264 (two 132-float halves)
    float* wgS = sm + 128 * 264;        // 2048

    int tid = threadIdx.x;
    int tok0 = blockIdx.x * 128;

    for (int i = tid; i < NE * DM; i += 256) wgS[i] = wg[i];
    for (int i = tid; i < 128 * DM; i += 256) {
        int r = i >> 8, c = i & 255;
        xS[r * 264 + (c >> 7) * 132 + (c & 127)] = x[(size_t)(tok0 + r) * DM + c];
    }
    __syncthreads();

    int r = tid >> 1, h = tid & 1;
    const float4* xr  = (const float4*)(xS + r * 264 + h * 132);
    const float4* wg4 = (const float4*)wgS;

    float acc[NE];
    #pragma unroll
    for (int e = 0; e < NE; e++) acc[e] = 0.f;
    #pragma unroll 4
    for (int k4 = 0; k4 < 32; k4++) {
        float4 xv = xr[k4];
        #pragma unroll
        for (int e = 0; e < NE; e++) {
            float4 w = wg4[e * 64 + h * 32 + k4];
            acc[e] += xv.x * w.x + xv.y * w.y + xv.z * w.z + xv.w * w.w;
        }
    }
    #pragma unroll
    for (int e = 0; e < NE; e++)
        acc[e] += __shfl_xor_sync(0xffffffffu, acc[e], 1);

    int lane = tid & 31;
    if ((lane & 1) == 0) {              // even lanes own tokens
        float mx = acc[0]; int a = 0;
        #pragma unroll
        for (int e = 1; e < NE; e++) if (acc[e] > mx) { mx = acc[e]; a = e; }
        float s = 0.f;
        #pragma unroll
        for (int e = 0; e < NE; e++) s += __expf(acc[e] - mx);
        float gate = 1.0f / s;

        unsigned grp = __match_any_sync(0x55555555u, a);
        int leader = __ffs(grp) - 1;
        int rank   = __popc(grp & ((1u << lane) - 1));
        int base = 0;
        if (lane == leader) base = atomicAdd(&g_cnt[a], __popc(grp));
        base = __shfl_sync(0x55555555u, base, leader);

        int tok = tok0 + r;
        g_assign[tok] = a;
        g_ticket[tok] = base + rank;
        g_gate[tok]   = gate;
    }
}

// ---------------- kernel 3/4: scan + perm -----------------------------------
__global__ void scan_kernel() {
    int s = 0;
    for (int e = 0; e < NE; e++) { g_off[e] = s; s += g_cnt[e]; }
}
__global__ void perm_kernel() {
    int i = blockIdx.x * blockDim.x + threadIdx.x;
    g_perm[g_off[g_assign[i]] + g_ticket[i]] = i;
}

// ---------------- GEMM pieces ------------------------------------------------
__device__ __forceinline__ void load_chunk(char* sraw, int buf,
                                           const float* src, int tid) {
    uint32_t d = smem_u32(sraw + SM_B + buf * CHUNK_BYTES) + tid * 16;
    const float4* s = (const float4*)src + tid;
    #pragma unroll
    for (int t = 0; t < 8; t++)
        cp_async16(d + t * 256 * 16, s + t * 256);
    cp_commit();
}

__device__ __forceinline__ void compute_chunk(
    const float4* __restrict__ A4, const float4* __restrict__ B4,
    float acc[2][8][4], int kk0, int mbase, int n0, int tg)
{
    #pragma unroll
    for (int u = 0; u < 2; u++) {
        const float4* Ak = A4 + (kk0 + u) * 256;
        const float4* Bk = B4 + u * 1024;
        float4 alo[2], ahi[2];
        #pragma unroll
        for (int mi = 0; mi < 2; mi++) {
            alo[mi] = Ak[(mbase + mi * 16) * 4 + tg];
            ahi[mi] = Ak[(mbase + mi * 16 + 8) * 4 + tg];
        }
        #pragma unroll
        for (int ni = 0; ni < 8; ni++) {
            float4 bv = Bk[(n0 + ni * 8) * 4 + tg];
            #pragma unroll
            for (int mi = 0; mi < 2; mi++) {
                mma_tf32(acc[mi][ni],
                         __float_as_uint(alo[mi].x), __float_as_uint(ahi[mi].x),
                         __float_as_uint(alo[mi].y), __float_as_uint(ahi[mi].y),
                         __float_as_uint(bv.x), __float_as_uint(bv.y));
                mma_tf32(acc[mi][ni],
                         __float_as_uint(alo[mi].z), __float_as_uint(ahi[mi].z),
                         __float_as_uint(alo[mi].w), __float_as_uint(ahi[mi].w),
                         __float_as_uint(bv.z), __float_as_uint(bv.w));
            }
        }
    }
}

// ---------------- kernel 5: grouped FFN --------------------------------------
__global__ void __launch_bounds__(GT, 1) moe_gemm_kernel(
    const float* __restrict__ x,
    const float* __restrict__ b1, const float* __restrict__ b2,
    float* __restrict__ out)
{
    int e = blockIdx.x >> 10;
    int t = blockIdx.x & (TPE - 1);
    int cnt = g_cnt[e];
    int m0 = t * MT;
    if (m0 >= cnt) return;
    int rows = min(MT, cnt - m0);
    int base = g_off[e] + m0;

    extern __shared__ char sraw[];
    int*   tokS  = (int*)(sraw + SM_TOK);
    float* gateS = (float*)(sraw + SM_GATE);
    float* biasS = (float*)(sraw + SM_BIAS);
    float* As    = (float*)(sraw + SM_A);
    float4* A4   = (float4*)As;

    int tid = threadIdx.x;
    int lane = tid & 31, warp = tid >> 5;
    int wm = warp & 1, wn = warp >> 1;
    int g = lane >> 2, tg = lane & 3;
    int mbase = wm * 32 + g;
    int n0 = wn * 64 + g;

    if (tid < MT) {
        int tok = (tid < rows) ? g_perm[base + tid] : -1;
        tokS[tid]  = tok;
        gateS[tid] = (tok >= 0) ? g_gate[tok] : 0.f;
    }
    for (int i = tid; i < DM; i += GT) {
        biasS[i]      = b1[e * DM + i];
        biasS[DM + i] = b2[e * DM + i];
    }
    __syncthreads();

    const float* wsrc = g_wimg + (size_t)e * NCHUNK_TOT * CHUNK_WORDS;
    #pragma unroll
    for (int c = 0; c < NBUF; c++)
        load_chunk(sraw, c, wsrc + (size_t)c * CHUNK_WORDS, tid);

    // ---- gather X into fragment layout: A'[kk][m][tg*4+c] = tf32(X[m][kk*16+c*4+tg])
    {
        int r = tid >> 2, q = tid & 3;
        int tok = tokS[r];
        const float4* xrow = (tok >= 0)
            ? (const float4*)(x + (size_t)tok * DM) : nullptr;
        #pragma unroll
        for (int kkl = 0; kkl < 4; kkl++) {
            int kk = q * 4 + kkl;
            float4 v[4];
            if (tok >= 0) {
                #pragma unroll
                for (int c = 0; c < 4; c++) v[c] = xrow[kk * 4 + c];
            } else {
                #pragma unroll
                for (int c = 0; c < 4; c++) v[c] = make_float4(0.f, 0.f, 0.f, 0.f);
            }
            float4 o;
            int ibase = kk * 256 + r * 4;
            o.x = __uint_as_float(f2tf32(v[0].x)); o.y = __uint_as_float(f2tf32(v[1].x));
            o.z = __uint_as_float(f2tf32(v[2].x)); o.w = __uint_as_float(f2tf32(v[3].x));
            A4[ibase + 0] = o;
            o.x = __uint_as_float(f2tf32(v[0].y)); o.y = __uint_as_float(f2tf32(v[1].y));
            o.z = __uint_as_float(f2tf32(v[2].y)); o.w = __uint_as_float(f2tf32(v[3].y));
            A4[ibase + 1] = o;
            o.x = __uint_as_float(f2tf32(v[0].z)); o.y = __uint_as_float(f2tf32(v[1].z));
            o.z = __uint_as_float(f2tf32(v[2].z)); o.w = __uint_as_float(f2tf32(v[3].z));
            A4[ibase + 2] = o;
            o.x = __uint_as_float(f2tf32(v[0].w)); o.y = __uint_as_float(f2tf32(v[1].w));
            o.z = __uint_as_float(f2tf32(v[2].w)); o.w = __uint_as_float(f2tf32(v[3].w));
            A4[ibase + 3] = o;
        }
    }
    __syncthreads();

    float acc[2][8][4];
    #pragma unroll
    for (int mi = 0; mi < 2; mi++)
        #pragma unroll
        for (int ni = 0; ni < 8; ni++)
            #pragma unroll
            for (int q = 0; q < 4; q++) acc[mi][ni][q] = 0.f;

    for (int i = 0; i < NCHUNK_TOT; i++) {
        if (i == 8) {
            // ---- epilogue 1: H = tf32(relu(D1 + b1)) into A' fragment layout
            #pragma unroll
            for (int mi = 0; mi < 2; mi++) {
                #pragma unroll
                for (int ni = 0; ni < 8; ni++) {
                    int col = wn * 64 + ni * 8 + tg * 2;
                    int r1  = mbase + mi * 16;
                    #pragma unroll
                    for (int dc = 0; dc < 2; dc++) {
                        int cc = col + dc;
                        int j  = (cc & 3) * 4 + ((cc >> 2) & 3);
                        float v0 = fmaxf(acc[mi][ni][dc]     + biasS[cc], 0.f);
                        float v1 = fmaxf(acc[mi][ni][2 + dc] + biasS[cc], 0.f);
                        As[((cc >> 4) << 10) + r1 * 16 + j]       = __uint_as_float(f2tf32(v0));
                        As[((cc >> 4) << 10) + (r1 + 8) * 16 + j] = __uint_as_float(f2tf32(v1));
                    }
                }
            }
            __syncthreads();
            #pragma unroll
            for (int mi = 0; mi < 2; mi++)
                #pragma unroll
                for (int ni = 0; ni < 8; ni++)
                    #pragma unroll
                    for (int q = 0; q < 4; q++) acc[mi][ni][q] = 0.f;
        }
        cp_wait3();
        __syncthreads();
        compute_chunk(A4, (const float4*)(sraw + SM_B + (i & 3) * CHUNK_BYTES),
                      acc, (i & 7) * 2, mbase, n0, tg);
        __syncthreads();
        if (i + NBUF < NCHUNK_TOT)
            load_chunk(sraw, i & 3, wsrc + (size_t)(i + NBUF) * CHUNK_WORDS, tid);
    }

    // ---- epilogue 2: out[tok] = (D2 + b2) * gate -----------------------------
    #pragma unroll
    for (int mi = 0; mi < 2; mi++) {
        #pragma unroll
        for (int rr = 0; rr < 2; rr++) {
            int row = mbase + mi * 16 + rr * 8;
            int tok = tokS[row];
            if (tok >= 0) {
                float gt = gateS[row];
                float* orow = out + (size_t)tok * DM;
                #pragma unroll
                for (int ni = 0; ni < 8; ni++) {
                    int col = wn * 64 + ni * 8 + tg * 2;
                    float2 v;
                    v.x = (acc[mi][ni][rr * 2 + 0] + biasS[DM + col])     * gt;
                    v.y = (acc[mi][ni][rr * 2 + 1] + biasS[DM + col + 1]) * gt;
                    *reinterpret_cast<float2*>(orow + col) = v;
                }
            }
        }
    }
}

// ---------------- launch -----------------------------------------------------
extern "C" void kernel_launch(void* const* d_in, const int* in_sizes, int n_in,
                              void* d_out, int out_size)
{
    const float* x  = (const float*)d_in[0];
    const float* wg = (const float*)d_in[1];
    const float* W1 = (const float*)d_in[2];
    const float* b1 = (const float*)d_in[3];
    const float* W2 = (const float*)d_in[4];
    const float* b2 = (const float*)d_in[5];
    float* out = (float*)d_out;

    const int rt_smem = (128 * 264 + NE * DM) * 4;
    cudaFuncSetAttribute(routing_kernel,
                         cudaFuncAttributeMaxDynamicSharedMemorySize, rt_smem);
    cudaFuncSetAttribute(moe_gemm_kernel,
                         cudaFuncAttributeMaxDynamicSharedMemorySize, SMEM_TOTAL);

    zero_kernel<<<1, 32>>>();
    wimg_kernel<<<NE * 16, 256>>>(W1, W2);
    routing_kernel<<<NTOK / 128, 256, rt_smem>>>(x, wg);
    scan_kernel<<<1, 1>>>();
    perm_kernel<<<64, 1024>>>();
    moe_gemm_kernel<<<NE * TPE, GT, SMEM_TOTAL>>>(x, b1, b2, out);
}

// round 5
// speedup vs baseline: 1.1232x; 1.1232x over previous
#include <cuda_runtime.h>
#include <cstdint>

#define NTOK 65536
#define DM   256
#define NE   8
#define MT   128
#define TPE  (NTOK / MT)          // 512
#define GT   512
#define KB   32
#define XS_STRIDE 260
#define WS_STRIDE 264

// ---------------- device scratch (no allocation allowed) -------------------
__device__ int   g_cnt[NE];
__device__ int   g_off[NE];
__device__ int   g_assign[NTOK];
__device__ int   g_ticket[NTOK];
__device__ float g_gate[NTOK];
__device__ int   g_perm[NTOK];

// ---------------- helpers ---------------------------------------------------
__device__ __forceinline__ uint32_t f2tf32(float f) {
    uint32_t r;
    asm("cvt.rna.tf32.f32 %0, %1;" : "=r"(r) : "f"(f));
    return r;
}
__device__ __forceinline__ void mma_tf32(float c[4], const uint32_t a[4],
                                         uint32_t b0, uint32_t b1) {
    asm volatile(
        "mma.sync.aligned.m16n8k8.row.col.f32.tf32.tf32.f32 "
        "{%0,%1,%2,%3}, {%4,%5,%6,%7}, {%8,%9}, {%0,%1,%2,%3};\n"
        : "+f"(c[0]), "+f"(c[1]), "+f"(c[2]), "+f"(c[3])
        : "r"(a[0]), "r"(a[1]), "r"(a[2]), "r"(a[3]), "r"(b0), "r"(b1));
}

// ---------------- kernel 0: zero counters ----------------------------------
__global__ void zero_kernel() {
    if (threadIdx.x < NE) g_cnt[threadIdx.x] = 0;
}

// ---------------- kernel 1: routing (2 threads per token) -------------------
__global__ void __launch_bounds__(256) routing_kernel(
    const float* __restrict__ x, const float* __restrict__ wg)
{
    extern __shared__ float sm[];
    float* xS  = sm;                    // 128 rows x 264 (two 132-float halves)
    float* wgS = sm + 128 * 264;        // 2048

    int tid = threadIdx.x;
    int tok0 = blockIdx.x * 128;

    for (int i = tid; i < NE * DM; i += 256) wgS[i] = wg[i];
    for (int i = tid; i < 128 * DM; i += 256) {
        int r = i >> 8, c = i & 255;
        xS[r * 264 + (c >> 7) * 132 + (c & 127)] = x[(size_t)(tok0 + r) * DM + c];
    }
    __syncthreads();

    int r = tid >> 1, h = tid & 1;
    const float4* xr  = (const float4*)(xS + r * 264 + h * 132);
    const float4* wg4 = (const float4*)wgS;

    float acc[NE];
    #pragma unroll
    for (int e = 0; e < NE; e++) acc[e] = 0.f;
    #pragma unroll 4
    for (int k4 = 0; k4 < 32; k4++) {
        float4 xv = xr[k4];
        #pragma unroll
        for (int e = 0; e < NE; e++) {
            float4 w = wg4[e * 64 + h * 32 + k4];
            acc[e] += xv.x * w.x + xv.y * w.y + xv.z * w.z + xv.w * w.w;
        }
    }
    #pragma unroll
    for (int e = 0; e < NE; e++)
        acc[e] += __shfl_xor_sync(0xffffffffu, acc[e], 1);

    int lane = tid & 31;
    if ((lane & 1) == 0) {
        float mx = acc[0]; int a = 0;
        #pragma unroll
        for (int e = 1; e < NE; e++) if (acc[e] > mx) { mx = acc[e]; a = e; }
        float s = 0.f;
        #pragma unroll
        for (int e = 0; e < NE; e++) s += __expf(acc[e] - mx);
        float gate = 1.0f / s;

        unsigned grp = __match_any_sync(0x55555555u, a);
        int leader = __ffs(grp) - 1;
        int rank   = __popc(grp & ((1u << lane) - 1));
        int base = 0;
        if (lane == leader) base = atomicAdd(&g_cnt[a], __popc(grp));
        base = __shfl_sync(0x55555555u, base, leader);

        int tok = tok0 + r;
        g_assign[tok] = a;
        g_ticket[tok] = base + rank;
        g_gate[tok]   = gate;
    }
}

// ---------------- kernel 2/3: scan + perm -----------------------------------
__global__ void scan_kernel() {
    int s = 0;
    for (int e = 0; e < NE; e++) { g_off[e] = s; s += g_cnt[e]; }
}
__global__ void perm_kernel() {
    int i = blockIdx.x * blockDim.x + threadIdx.x;
    g_perm[g_off[g_assign[i]] + g_ticket[i]] = i;
}

// ---------------- GEMM pieces (R1-proven inner structure, 512 threads) ------
__device__ __forceinline__ void ldg_chunk(const float* __restrict__ Wg, int kb,
                                          int tid, float4 w[4]) {
    #pragma unroll
    for (int j = 0; j < 4; j++) {
        int i = tid + j * GT;
        int r = i >> 6, c4 = i & 63;
        w[j] = *reinterpret_cast<const float4*>(Wg + (kb * KB + r) * DM + c4 * 4);
    }
}

__device__ __forceinline__ void sts_chunk(float* __restrict__ Wbuf, int tid,
                                          const float4 w[4]) {
    #pragma unroll
    for (int j = 0; j < 4; j++) {
        int i = tid + j * GT;
        int r = i >> 6, c4 = i & 63;
        float* p = Wbuf + r * WS_STRIDE + c4 * 4;
        p[0] = __uint_as_float(f2tf32(w[j].x));
        p[1] = __uint_as_float(f2tf32(w[j].y));
        p[2] = __uint_as_float(f2tf32(w[j].z));
        p[3] = __uint_as_float(f2tf32(w[j].w));
    }
}

__device__ __forceinline__ void compute_chunk(
    const float* __restrict__ Xs, const float* __restrict__ Wb,
    float acc[2][8][4], int kbase, int wm, int wn, int g, int tg)
{
    #pragma unroll
    for (int k8 = 0; k8 < KB / 8; k8++) {
        int k = k8 * 8;
        uint32_t a[2][4];
        #pragma unroll
        for (int mi = 0; mi < 2; mi++) {
            const float* xr = Xs + (wm * 32 + mi * 16 + g) * XS_STRIDE + kbase + k + tg;
            a[mi][0] = __float_as_uint(xr[0]);
            a[mi][1] = __float_as_uint(xr[8 * XS_STRIDE]);
            a[mi][2] = __float_as_uint(xr[4]);
            a[mi][3] = __float_as_uint(xr[8 * XS_STRIDE + 4]);
        }
        #pragma unroll
        for (int ni = 0; ni < 8; ni++) {
            int bc = wn * 64 + ni * 8 + g;
            uint32_t b0 = __float_as_uint(Wb[(k + tg) * WS_STRIDE + bc]);
            uint32_t b1 = __float_as_uint(Wb[(k + tg + 4) * WS_STRIDE + bc]);
            mma_tf32(acc[0][ni], a[0], b0, b1);
            mma_tf32(acc[1][ni], a[1], b0, b1);
        }
    }
}

__device__ __forceinline__ void run_stage(
    const float* __restrict__ Wg, const float* __restrict__ Xs,
    float* __restrict__ Ws, float acc[2][8][4],
    int tid, int wm, int wn, int g, int tg)
{
    #pragma unroll
    for (int mi = 0; mi < 2; mi++)
        #pragma unroll
        for (int ni = 0; ni < 8; ni++)
            #pragma unroll
            for (int q = 0; q < 4; q++) acc[mi][ni][q] = 0.f;

    float4 w[4];
    ldg_chunk(Wg, 0, tid, w);
    sts_chunk(Ws, tid, w);
    __syncthreads();

    #pragma unroll
    for (int kb = 0; kb < DM / KB; kb++) {
        if (kb + 1 < DM / KB) ldg_chunk(Wg, kb + 1, tid, w);
        compute_chunk(Xs, Ws + (kb & 1) * (KB * WS_STRIDE), acc, kb * KB, wm, wn, g, tg);
        if (kb + 1 < DM / KB) {
            sts_chunk(Ws + ((kb + 1) & 1) * (KB * WS_STRIDE), tid, w);
            __syncthreads();
        }
    }
}

// ---------------- kernel 4: grouped GEMM (gather -> FFN -> scatter) ---------
__global__ void __launch_bounds__(GT, 1) moe_gemm_kernel(
    const float* __restrict__ x,
    const float* __restrict__ W1, const float* __restrict__ b1,
    const float* __restrict__ W2, const float* __restrict__ b2,
    float* __restrict__ out)
{
    int e = blockIdx.x >> 9;               // / TPE
    int t = blockIdx.x & (TPE - 1);
    int cnt = g_cnt[e];
    int m0 = t * MT;
    if (m0 >= cnt) return;
    int rows = min(MT, cnt - m0);
    int base = g_off[e] + m0;

    extern __shared__ float smem[];
    float* Xs    = smem;                         // MT * XS_STRIDE
    float* Ws    = Xs + MT * XS_STRIDE;          // 2 * KB * WS_STRIDE
    float* gateS = Ws + 2 * KB * WS_STRIDE;      // MT
    float* biasS = gateS + MT;                   // DM
    int*   tokS  = (int*)(biasS + DM);           // MT

    int tid  = threadIdx.x;
    int lane = tid & 31, warp = tid >> 5;
    int wm = warp & 3, wn = warp >> 2;           // 4x4 warp grid
    int g = lane >> 2, tg = lane & 3;

    if (tid < MT) {
        int tok = (tid < rows) ? g_perm[base + tid] : -1;
        tokS[tid]  = tok;
        gateS[tid] = (tok >= 0) ? g_gate[tok] : 0.f;
    }
    for (int i = tid; i < DM; i += GT) biasS[i] = b1[e * DM + i];
    __syncthreads();

    // gather X tile (zero-pad invalid rows), convert to tf32
    #pragma unroll
    for (int j = 0; j < MT * 64 / GT; j++) {
        int i = tid + j * GT;
        int r = i >> 6, c4 = i & 63;
        float4 v = make_float4(0.f, 0.f, 0.f, 0.f);
        int tok = tokS[r];
        if (tok >= 0)
            v = *reinterpret_cast<const float4*>(x + (size_t)tok * DM + c4 * 4);
        float* p = Xs + r * XS_STRIDE + c4 * 4;
        p[0] = __uint_as_float(f2tf32(v.x));
        p[1] = __uint_as_float(f2tf32(v.y));
        p[2] = __uint_as_float(f2tf32(v.z));
        p[3] = __uint_as_float(f2tf32(v.w));
    }
    __syncthreads();

    float acc[2][8][4];
    const float* W1e = W1 + (size_t)e * DM * DM;
    run_stage(W1e, Xs, Ws, acc, tid, wm, wn, g, tg);

    __syncthreads();

    // epilogue 1: relu(acc + b1) -> Xs (as tf32)
    #pragma unroll
    for (int mi = 0; mi < 2; mi++) {
        #pragma unroll
        for (int ni = 0; ni < 8; ni++) {
            int col = wn * 64 + ni * 8 + tg * 2;
            int r0  = wm * 32 + mi * 16 + g;
            float bq0 = biasS[col], bq1 = biasS[col + 1];
            float v00 = fmaxf(acc[mi][ni][0] + bq0, 0.f);
            float v01 = fmaxf(acc[mi][ni][1] + bq1, 0.f);
            float v10 = fmaxf(acc[mi][ni][2] + bq0, 0.f);
            float v11 = fmaxf(acc[mi][ni][3] + bq1, 0.f);
            Xs[r0 * XS_STRIDE + col]           = __uint_as_float(f2tf32(v00));
            Xs[r0 * XS_STRIDE + col + 1]       = __uint_as_float(f2tf32(v01));
            Xs[(r0 + 8) * XS_STRIDE + col]     = __uint_as_float(f2tf32(v10));
            Xs[(r0 + 8) * XS_STRIDE + col + 1] = __uint_as_float(f2tf32(v11));
        }
    }
    __syncthreads();
    for (int i = tid; i < DM; i += GT) biasS[i] = b2[e * DM + i];
    // biasS not read again until after run_stage (which syncs internally)

    const float* W2e = W2 + (size_t)e * DM * DM;
    run_stage(W2e, Xs, Ws, acc, tid, wm, wn, g, tg);

    // epilogue 2: (acc + b2) * gate -> scatter rows
    #pragma unroll
    for (int mi = 0; mi < 2; mi++) {
        #pragma unroll
        for (int rr = 0; rr < 2; rr++) {
            int r = wm * 32 + mi * 16 + rr * 8 + g;
            if (r < rows) {
                int tok  = tokS[r];
                float gt = gateS[r];
                float* orow = out + (size_t)tok * DM;
                #pragma unroll
                for (int ni = 0; ni < 8; ni++) {
                    int col = wn * 64 + ni * 8 + tg * 2;
                    float2 v;
                    v.x = (acc[mi][ni][rr * 2 + 0] + biasS[col])     * gt;
                    v.y = (acc[mi][ni][rr * 2 + 1] + biasS[col + 1]) * gt;
                    *reinterpret_cast<float2*>(orow + col) = v;
                }
            }
        }
    }
}

// ---------------- kernel 5: profiling tail (ncu samples 2nd-to-last) --------
__global__ void tail_kernel() {}

// ---------------- launch -----------------------------------------------------
extern "C" void kernel_launch(void* const* d_in, const int* in_sizes, int n_in,
                              void* d_out, int out_size)
{
    const float* x  = (const float*)d_in[0];
    const float* wg = (const float*)d_in[1];
    const float* W1 = (const float*)d_in[2];
    const float* b1 = (const float*)d_in[3];
    const float* W2 = (const float*)d_in[4];
    const float* b2 = (const float*)d_in[5];
    float* out = (float*)d_out;

    const int rt_smem = (128 * 264 + NE * DM) * 4;
    const int gm_smem = (MT * XS_STRIDE + 2 * KB * WS_STRIDE + MT + DM + MT) * 4;
    cudaFuncSetAttribute(routing_kernel,
                         cudaFuncAttributeMaxDynamicSharedMemorySize, rt_smem);
    cudaFuncSetAttribute(moe_gemm_kernel,
                         cudaFuncAttributeMaxDynamicSharedMemorySize, gm_smem);

    zero_kernel<<<1, 32>>>();
    routing_kernel<<<NTOK / 128, 256, rt_smem>>>(x, wg);
    scan_kernel<<<1, 1>>>();
    perm_kernel<<<64, 1024>>>();
    moe_gemm_kernel<<<NE * TPE, GT, gm_smem>>>(x, W1, b1, W2, b2, out);
    tail_kernel<<<1, 32>>>();
}